// round 6
// baseline (speedup 1.0000x reference)
#include <cuda_runtime.h>
#include <cstdint>

// Problem constants (fixed by the dataset)
#define MAXN 100000
#define MAXE 1600000

// ---------------- scratch (device globals; no allocs allowed) ----------------
__device__ float g_m[MAXN * 64];      // pool-transformed features
__device__ float g_h1[MAXN * 64];     // layer-1 output
__device__ float g_h2[MAXN * 32];     // layer-2 output
__device__ int   g_rowptr[MAXN + 1];
__device__ int   g_deg[MAXN];         // degree, then reused as scatter cursor
__device__ int   g_csrc[MAXE];        // CSR src ids, grouped by dst

// ---------------- f32x2 packed-FMA helpers (sm_100+) ----------------
__device__ __forceinline__ unsigned long long pk2(float lo, float hi) {
    unsigned long long r;
    asm("mov.b64 %0,{%1,%2};" : "=l"(r) : "f"(lo), "f"(hi));
    return r;
}
__device__ __forceinline__ void fma2(unsigned long long& d, unsigned long long a,
                                     unsigned long long b) {
    asm("fma.rn.f32x2 %0, %1, %2, %0;" : "+l"(d) : "l"(a), "l"(b));
}
__device__ __forceinline__ void upk2(unsigned long long v, float& lo, float& hi) {
    asm("mov.b64 {%0,%1},%2;" : "=f"(lo), "=f"(hi) : "l"(v));
}

// ---------------- CSR build ----------------
__global__ void k_hist(const int* __restrict__ dst, int* __restrict__ deg, int E, int N) {
    int i = blockIdx.x * blockDim.x + threadIdx.x;
    int e = i * 4;
    if (e + 3 < E) {
        int4 d4 = *reinterpret_cast<const int4*>(&dst[e]);
        if (d4.x >= 0 && d4.x < N) atomicAdd(&deg[d4.x], 1);
        if (d4.y >= 0 && d4.y < N) atomicAdd(&deg[d4.y], 1);
        if (d4.z >= 0 && d4.z < N) atomicAdd(&deg[d4.z], 1);
        if (d4.w >= 0 && d4.w < N) atomicAdd(&deg[d4.w], 1);
    } else {
        for (int k = e; k < E; k++) {
            int d = dst[k];
            if (d >= 0 && d < N) atomicAdd(&deg[d], 1);
        }
    }
}

// fused scan: one block, 1024 threads, chunked serial + block-scan of partials.
// Writes rowptr (exclusive) and cursor (= rowptr copy; may alias deg input).
__global__ void __launch_bounds__(1024) k_scanfused(const int* __restrict__ deg,
                                                    int* __restrict__ rowptr,
                                                    int* __restrict__ cursor,
                                                    int n, int E) {
    __shared__ int sh[1024];
    int tid = threadIdx.x;
    int chunk = (n + 1023) / 1024;
    int beg = tid * chunk;
    int end = beg + chunk < n ? beg + chunk : n;
    int sum = 0;
    for (int i = beg; i < end; i++) sum += deg[i];
    sh[tid] = sum;
    __syncthreads();
    int inc = sum;
#pragma unroll
    for (int off = 1; off < 1024; off <<= 1) {
        int t = (tid >= off) ? sh[tid - off] : 0;
        __syncthreads();
        sh[tid] += t;
        __syncthreads();
    }
    inc = sh[tid];
    int run = inc - sum;  // exclusive prefix for this chunk
    for (int i = beg; i < end; i++) {
        int d = deg[i];   // read BEFORE write (cursor may alias deg)
        rowptr[i] = run;
        cursor[i] = run;
        run += d;
    }
    if (tid == 0) rowptr[n] = E;
}

__global__ void k_scatter(const int* __restrict__ src, const int* __restrict__ dst,
                          int* __restrict__ cursor, int* __restrict__ csrc, int E, int N) {
    int i = blockIdx.x * blockDim.x + threadIdx.x;
    int e = i * 4;
    if (e + 3 < E) {
        int4 s4 = *reinterpret_cast<const int4*>(&src[e]);
        int4 d4 = *reinterpret_cast<const int4*>(&dst[e]);
        if (d4.x >= 0 && d4.x < N) csrc[atomicAdd(&cursor[d4.x], 1)] = s4.x;
        if (d4.y >= 0 && d4.y < N) csrc[atomicAdd(&cursor[d4.y], 1)] = s4.y;
        if (d4.z >= 0 && d4.z < N) csrc[atomicAdd(&cursor[d4.z], 1)] = s4.z;
        if (d4.w >= 0 && d4.w < N) csrc[atomicAdd(&cursor[d4.w], 1)] = s4.w;
    } else {
        for (int k = e; k < E; k++) {
            int d = dst[k];
            if (d >= 0 && d < N) csrc[atomicAdd(&cursor[d], 1)] = src[k];
        }
    }
}

// ---------------- pool GEMM (single matrix): out = relu(A@W + b) ----------------
// 256 threads; 128 nodes/block; per-thread tile: 4 nodes x 8 outs.
template <int IN, int OUT>
__global__ void __launch_bounds__(256) k_gemm_pool(const float* __restrict__ A,
                                                   const float* __restrict__ W,
                                                   const float* __restrict__ bias,
                                                   float* __restrict__ out, int n) {
    constexpr int NPB = 128;
    constexpr int TJ = OUT / 8;
    constexpr int NP = TJ / 2;
    constexpr int LDA = IN + 2;
    extern __shared__ float sm[];
    float* sW = sm;              // IN*OUT
    float* sB = sm + IN * OUT;   // OUT
    float* sA = sB + OUT;        // NPB*LDA

    int tid = threadIdx.x;
    for (int i = tid; i < IN * OUT; i += 256) sW[i] = W[i];
    for (int i = tid; i < OUT; i += 256) sB[i] = bias[i];

    int base = blockIdx.x * NPB;
    for (int i = tid; i < NPB * IN; i += 256) {
        int nn = i / IN, kk = i % IN;
        sA[nn * LDA + kk] = (base + nn < n) ? A[(size_t)(base + nn) * IN + kk] : 0.f;
    }
    __syncthreads();

    int jg = tid & 7;
    int ng = tid >> 3;
    unsigned long long acc2[4][NP];
#pragma unroll
    for (int i = 0; i < 4; i++)
#pragma unroll
        for (int j = 0; j < NP; j++) acc2[i][j] = 0ull;

    const float* sAr = sA + (ng * 4) * LDA;
#pragma unroll 4
    for (int k = 0; k < IN; k += 2) {
        float2 xv[4];
#pragma unroll
        for (int i = 0; i < 4; i++)
            xv[i] = *reinterpret_cast<const float2*>(&sAr[i * LDA + k]);
        unsigned long long wv0[NP], wv1[NP];
#pragma unroll
        for (int p = 0; p < NP; p += 2) {
            float4 w = *reinterpret_cast<const float4*>(&sW[k * OUT + jg * TJ + 2 * p]);
            wv0[p] = pk2(w.x, w.y);
            if (p + 1 < NP) wv0[p + 1] = pk2(w.z, w.w);
        }
#pragma unroll
        for (int p = 0; p < NP; p += 2) {
            float4 w = *reinterpret_cast<const float4*>(&sW[(k + 1) * OUT + jg * TJ + 2 * p]);
            wv1[p] = pk2(w.x, w.y);
            if (p + 1 < NP) wv1[p + 1] = pk2(w.z, w.w);
        }
#pragma unroll
        for (int i = 0; i < 4; i++) {
            unsigned long long a0 = pk2(xv[i].x, xv[i].x);
            unsigned long long a1 = pk2(xv[i].y, xv[i].y);
#pragma unroll
            for (int j = 0; j < NP; j++) {
                fma2(acc2[i][j], a0, wv0[j]);
                fma2(acc2[i][j], a1, wv1[j]);
            }
        }
    }

#pragma unroll
    for (int i = 0; i < 4; i++) {
        int node = base + ng * 4 + i;
        if (node < n) {
#pragma unroll
            for (int j = 0; j < NP; j++) {
                float lo, hi;
                upk2(acc2[i][j], lo, hi);
                float v0 = fmaxf(lo + sB[jg * TJ + 2 * j], 0.f);
                float v1 = fmaxf(hi + sB[jg * TJ + 2 * j + 1], 0.f);
                out[(size_t)node * OUT + jg * TJ + 2 * j] = v0;
                out[(size_t)node * OUT + jg * TJ + 2 * j + 1] = v1;
            }
        }
    }
}

// ---------------- fused gather + dual GEMM ----------------
// out = [relu]( A@Wself + AGG@Wneigh + b )
// AGG gathered in-block from feat (max if !MEAN — relies on feat >= 0; mean if MEAN).
// IN = feature dim of A and feat (64 or 32). NPB=128 nodes, 256 threads.
template <int IN, int OUT, bool RELU, bool MEAN>
__global__ void __launch_bounds__(256) k_gemm_gather(
    const float* __restrict__ A, const float* __restrict__ Wself,
    const float4* __restrict__ feat4, const float* __restrict__ Wneigh,
    const float* __restrict__ bias, float* __restrict__ out,
    const int* __restrict__ rowptr, const int* __restrict__ srcs, int n) {
    constexpr int NPB = 128;
    constexpr int TJ = OUT / 8;
    constexpr int NP = TJ / 2;
    constexpr int LDA = IN + 6;    // even (f32x2 loads), row stride mod 32 banks = 24
    extern __shared__ float sm[];
    float* sW1 = sm;                  // IN*OUT (self)
    float* sW2 = sm + IN * OUT;       // IN*OUT (neigh)
    float* sB = sW2 + IN * OUT;       // OUT
    float* sA = sB + OUT;             // NPB*LDA

    int tid = threadIdx.x;
    for (int i = tid; i < IN * OUT; i += 256) {
        sW1[i] = Wself[i];
        sW2[i] = Wneigh[i];
    }
    for (int i = tid; i < OUT; i += 256) sB[i] = bias[i];

    int base = blockIdx.x * NPB;
    for (int i = tid; i < NPB * IN; i += 256) {
        int nn = i / IN, kk = i % IN;
        sA[nn * LDA + kk] = (base + nn < n) ? A[(size_t)(base + nn) * IN + kk] : 0.f;
    }
    __syncthreads();

    int jg = tid & 7;
    int ng = tid >> 3;
    unsigned long long acc2[4][NP];
#pragma unroll
    for (int i = 0; i < 4; i++)
#pragma unroll
        for (int j = 0; j < NP; j++) acc2[i][j] = 0ull;

    const float* sAr = sA + (ng * 4) * LDA;

    // ---- GEMM pass 1: self ----
    {
        const float* sW = sW1;
#pragma unroll 4
        for (int k = 0; k < IN; k += 2) {
            float2 xv[4];
#pragma unroll
            for (int i = 0; i < 4; i++)
                xv[i] = *reinterpret_cast<const float2*>(&sAr[i * LDA + k]);
            unsigned long long wv0[NP], wv1[NP];
#pragma unroll
            for (int p = 0; p < NP; p += 2) {
                float4 w = *reinterpret_cast<const float4*>(&sW[k * OUT + jg * TJ + 2 * p]);
                wv0[p] = pk2(w.x, w.y);
                if (p + 1 < NP) wv0[p + 1] = pk2(w.z, w.w);
            }
#pragma unroll
            for (int p = 0; p < NP; p += 2) {
                float4 w = *reinterpret_cast<const float4*>(&sW[(k + 1) * OUT + jg * TJ + 2 * p]);
                wv1[p] = pk2(w.x, w.y);
                if (p + 1 < NP) wv1[p + 1] = pk2(w.z, w.w);
            }
#pragma unroll
            for (int i = 0; i < 4; i++) {
                unsigned long long a0 = pk2(xv[i].x, xv[i].x);
                unsigned long long a1 = pk2(xv[i].y, xv[i].y);
#pragma unroll
                for (int j = 0; j < NP; j++) {
                    fma2(acc2[i][j], a0, wv0[j]);
                    fma2(acc2[i][j], a1, wv1[j]);
                }
            }
        }
    }
    __syncthreads();  // done reading A tile

    // ---- gather aggregated neighbor features into sA ----
    {
        int wid = tid >> 5, lane = tid & 31;
        if (!MEAN) {
            // 64-dim max: half-warp per edge, 16 lanes x float4 = 256B row
            int half = lane >> 4, sub = lane & 15;
            for (int nn = wid; nn < NPB; nn += 8) {
                int node = base + nn;
                float4 a = make_float4(0.f, 0.f, 0.f, 0.f);
                if (node < n) {
                    int beg = rowptr[node], end = rowptr[node + 1];
                    for (int e = beg + half; e < end; e += 2) {
                        int s = __ldg(&srcs[e]);
                        float4 t = feat4[(size_t)s * 16 + sub];
                        a.x = fmaxf(a.x, t.x);
                        a.y = fmaxf(a.y, t.y);
                        a.z = fmaxf(a.z, t.z);
                        a.w = fmaxf(a.w, t.w);
                    }
                }
                a.x = fmaxf(a.x, __shfl_xor_sync(0xffffffffu, a.x, 16));
                a.y = fmaxf(a.y, __shfl_xor_sync(0xffffffffu, a.y, 16));
                a.z = fmaxf(a.z, __shfl_xor_sync(0xffffffffu, a.z, 16));
                a.w = fmaxf(a.w, __shfl_xor_sync(0xffffffffu, a.w, 16));
                if (half == 0) {
                    float* p = &sA[nn * LDA + sub * 4];
                    *reinterpret_cast<float2*>(p) = make_float2(a.x, a.y);
                    *reinterpret_cast<float2*>(p + 2) = make_float2(a.z, a.w);
                }
            }
        } else {
            // 32-dim mean: quarter-warp per edge, 8 lanes x float4 = 128B row
            int q = lane >> 3, sub = lane & 7;
            for (int nn = wid; nn < NPB; nn += 8) {
                int node = base + nn;
                float4 a = make_float4(0.f, 0.f, 0.f, 0.f);
                float cnt = 0.f;
                if (node < n) {
                    int beg = rowptr[node], end = rowptr[node + 1];
                    cnt = (float)(end - beg);
                    for (int e = beg + q; e < end; e += 4) {
                        int s = __ldg(&srcs[e]);
                        float4 t = feat4[(size_t)s * 8 + sub];
                        a.x += t.x; a.y += t.y; a.z += t.z; a.w += t.w;
                    }
                }
#pragma unroll
                for (int off = 8; off <= 16; off <<= 1) {
                    a.x += __shfl_xor_sync(0xffffffffu, a.x, off);
                    a.y += __shfl_xor_sync(0xffffffffu, a.y, off);
                    a.z += __shfl_xor_sync(0xffffffffu, a.z, off);
                    a.w += __shfl_xor_sync(0xffffffffu, a.w, off);
                }
                if (q == 0) {
                    float inv = 1.f / fmaxf(cnt, 1.f);
                    float* p = &sA[nn * LDA + sub * 4];
                    *reinterpret_cast<float2*>(p) = make_float2(a.x * inv, a.y * inv);
                    *reinterpret_cast<float2*>(p + 2) = make_float2(a.z * inv, a.w * inv);
                }
            }
        }
    }
    __syncthreads();

    // ---- GEMM pass 2: neighbor aggregate ----
    {
        const float* sW = sW2;
#pragma unroll 4
        for (int k = 0; k < IN; k += 2) {
            float2 xv[4];
#pragma unroll
            for (int i = 0; i < 4; i++)
                xv[i] = *reinterpret_cast<const float2*>(&sAr[i * LDA + k]);
            unsigned long long wv0[NP], wv1[NP];
#pragma unroll
            for (int p = 0; p < NP; p += 2) {
                float4 w = *reinterpret_cast<const float4*>(&sW[k * OUT + jg * TJ + 2 * p]);
                wv0[p] = pk2(w.x, w.y);
                if (p + 1 < NP) wv0[p + 1] = pk2(w.z, w.w);
            }
#pragma unroll
            for (int p = 0; p < NP; p += 2) {
                float4 w = *reinterpret_cast<const float4*>(&sW[(k + 1) * OUT + jg * TJ + 2 * p]);
                wv1[p] = pk2(w.x, w.y);
                if (p + 1 < NP) wv1[p + 1] = pk2(w.z, w.w);
            }
#pragma unroll
            for (int i = 0; i < 4; i++) {
                unsigned long long a0 = pk2(xv[i].x, xv[i].x);
                unsigned long long a1 = pk2(xv[i].y, xv[i].y);
#pragma unroll
                for (int j = 0; j < NP; j++) {
                    fma2(acc2[i][j], a0, wv0[j]);
                    fma2(acc2[i][j], a1, wv1[j]);
                }
            }
        }
    }

#pragma unroll
    for (int i = 0; i < 4; i++) {
        int node = base + ng * 4 + i;
        if (node < n) {
#pragma unroll
            for (int j = 0; j < NP; j++) {
                float lo, hi;
                upk2(acc2[i][j], lo, hi);
                float v0 = lo + sB[jg * TJ + 2 * j];
                float v1 = hi + sB[jg * TJ + 2 * j + 1];
                if (RELU) { v0 = fmaxf(v0, 0.f); v1 = fmaxf(v1, 0.f); }
                out[(size_t)node * OUT + jg * TJ + 2 * j] = v0;
                out[(size_t)node * OUT + jg * TJ + 2 * j + 1] = v1;
            }
        }
    }
}

// ---------------- host launch ----------------
static inline int smem_pool(int IN, int OUT) {
    return (IN * OUT + OUT + 128 * (IN + 2)) * (int)sizeof(float);
}
static inline int smem_gather(int IN, int OUT) {
    return (2 * IN * OUT + OUT + 128 * (IN + 6)) * (int)sizeof(float);
}

extern "C" void kernel_launch(void* const* d_in, const int* in_sizes, int n_in,
                              void* d_out, int out_size) {
    const float* x        = (const float*)d_in[0];
    const int*   ei       = (const int*)d_in[1];   // int32 (JAX x64 disabled)
    const float* W1_pool  = (const float*)d_in[2];
    const float* b1_pool  = (const float*)d_in[3];
    const float* W1_self  = (const float*)d_in[4];
    const float* W1_neigh = (const float*)d_in[5];
    const float* b1       = (const float*)d_in[6];
    const float* W2_pool  = (const float*)d_in[7];
    const float* b2_pool  = (const float*)d_in[8];
    const float* W2_self  = (const float*)d_in[9];
    const float* W2_neigh = (const float*)d_in[10];
    const float* b2       = (const float*)d_in[11];
    const float* W3_self  = (const float*)d_in[12];
    const float* W3_neigh = (const float*)d_in[13];
    const float* b3       = (const float*)d_in[14];

    int N = in_sizes[0] / 64;
    int E = in_sizes[1] / 2;
    if (N > MAXN) N = MAXN;
    if (E > MAXE) E = MAXE;

    const int* src = ei;        // row 0
    const int* dst = ei + E;    // row 1

    float *m, *h1, *h2;
    int *rowptr, *deg, *csrc;
    cudaGetSymbolAddress((void**)&m, g_m);
    cudaGetSymbolAddress((void**)&h1, g_h1);
    cudaGetSymbolAddress((void**)&h2, g_h2);
    cudaGetSymbolAddress((void**)&rowptr, g_rowptr);
    cudaGetSymbolAddress((void**)&deg, g_deg);
    cudaGetSymbolAddress((void**)&csrc, g_csrc);

    cudaFuncSetAttribute((const void*)k_gemm_pool<64, 64>,
                         cudaFuncAttributeMaxDynamicSharedMemorySize, smem_pool(64, 64));
    cudaFuncSetAttribute((const void*)k_gemm_gather<64, 64, true, false>,
                         cudaFuncAttributeMaxDynamicSharedMemorySize, smem_gather(64, 64));
    cudaFuncSetAttribute((const void*)k_gemm_gather<64, 32, false, false>,
                         cudaFuncAttributeMaxDynamicSharedMemorySize, smem_gather(64, 32));
    cudaFuncSetAttribute((const void*)k_gemm_gather<32, 32, false, true>,
                         cudaFuncAttributeMaxDynamicSharedMemorySize, smem_gather(32, 32));

    int e4blocks = ((E + 3) / 4 + 255) / 256;
    int nblocks128 = (N + 127) / 128;

    // ---- CSR build (4 steps) ----
    cudaMemsetAsync(deg, 0, (size_t)N * sizeof(int));
    k_hist<<<e4blocks, 256>>>(dst, deg, E, N);
    k_scanfused<<<1, 1024>>>(deg, rowptr, deg, N, E);  // deg becomes cursor
    k_scatter<<<e4blocks, 256>>>(src, dst, deg, csrc, E, N);

    // ---- layer 1 (pool) ----
    k_gemm_pool<64, 64><<<nblocks128, 256, smem_pool(64, 64)>>>(x, W1_pool, b1_pool, m, N);
    k_gemm_gather<64, 64, true, false><<<nblocks128, 256, smem_gather(64, 64)>>>(
        x, W1_self, (const float4*)m, W1_neigh, b1, h1, rowptr, csrc, N);

    // ---- layer 2 (pool) ----
    k_gemm_pool<64, 64><<<nblocks128, 256, smem_pool(64, 64)>>>(h1, W2_pool, b2_pool, m, N);
    k_gemm_gather<64, 32, false, false><<<nblocks128, 256, smem_gather(64, 32)>>>(
        h1, W2_self, (const float4*)m, W2_neigh, b2, h2, rowptr, csrc, N);

    // ---- layer 3 (mean) ----
    k_gemm_gather<32, 32, false, true><<<nblocks128, 256, smem_gather(32, 32)>>>(
        h2, W3_self, (const float4*)h2, W3_neigh, b3, (float*)d_out, rowptr, csrc, N);
}

// round 7
// speedup vs baseline: 1.0508x; 1.0508x over previous
#include <cuda_runtime.h>
#include <cstdint>

#define MAXN 100000
#define MAXE 1600000

// ---------------- scratch (device globals; no allocs allowed) ----------------
__device__ float g_m[MAXN * 64];      // pool-transformed features
__device__ float g_agg[MAXN * 64];    // aggregated features
__device__ float g_h1[MAXN * 64];     // layer-1 output
__device__ float g_h2[MAXN * 32];     // layer-2 output
__device__ float g_agg3[MAXN * 32];   // layer-3 mean aggregate
__device__ int   g_rowptr[MAXN + 1];
__device__ int   g_deg[MAXN];         // degree, then reused as scatter cursor
__device__ int   g_csrc[MAXE];        // CSR src ids, grouped by dst

// ---------------- f32x2 packed-FMA helpers (sm_100+) ----------------
__device__ __forceinline__ unsigned long long pk2(float lo, float hi) {
    unsigned long long r;
    asm("mov.b64 %0,{%1,%2};" : "=l"(r) : "f"(lo), "f"(hi));
    return r;
}
__device__ __forceinline__ void fma2(unsigned long long& d, unsigned long long a,
                                     unsigned long long b) {
    asm("fma.rn.f32x2 %0, %1, %2, %0;" : "+l"(d) : "l"(a), "l"(b));
}
__device__ __forceinline__ void upk2(unsigned long long v, float& lo, float& hi) {
    asm("mov.b64 {%0,%1},%2;" : "=f"(lo), "=f"(hi) : "l"(v));
}

// ---------------- CSR build ----------------
__global__ void k_hist(const int* __restrict__ dst, int* __restrict__ deg, int E, int N) {
    int i = blockIdx.x * blockDim.x + threadIdx.x;
    int e = i * 4;
    if (e + 3 < E) {
        int4 d4 = *reinterpret_cast<const int4*>(&dst[e]);
        if (d4.x >= 0 && d4.x < N) atomicAdd(&deg[d4.x], 1);
        if (d4.y >= 0 && d4.y < N) atomicAdd(&deg[d4.y], 1);
        if (d4.z >= 0 && d4.z < N) atomicAdd(&deg[d4.z], 1);
        if (d4.w >= 0 && d4.w < N) atomicAdd(&deg[d4.w], 1);
    } else {
        for (int k = e; k < E; k++) {
            int d = dst[k];
            if (d >= 0 && d < N) atomicAdd(&deg[d], 1);
        }
    }
}

// fused scan: one block, 1024 threads, chunked serial + block-scan of partials.
__global__ void __launch_bounds__(1024) k_scanfused(const int* __restrict__ deg,
                                                    int* __restrict__ rowptr,
                                                    int* __restrict__ cursor,
                                                    int n, int E) {
    __shared__ int sh[1024];
    int tid = threadIdx.x;
    int chunk = (n + 1023) / 1024;
    int beg = tid * chunk;
    int end = beg + chunk < n ? beg + chunk : n;
    int sum = 0;
    for (int i = beg; i < end; i++) sum += deg[i];
    sh[tid] = sum;
    __syncthreads();
#pragma unroll
    for (int off = 1; off < 1024; off <<= 1) {
        int t = (tid >= off) ? sh[tid - off] : 0;
        __syncthreads();
        sh[tid] += t;
        __syncthreads();
    }
    int run = sh[tid] - sum;  // exclusive prefix for this chunk
    for (int i = beg; i < end; i++) {
        int d = deg[i];   // read BEFORE write (cursor may alias deg)
        rowptr[i] = run;
        cursor[i] = run;
        run += d;
    }
    if (tid == 0) rowptr[n] = E;
}

__global__ void k_scatter(const int* __restrict__ src, const int* __restrict__ dst,
                          int* __restrict__ cursor, int* __restrict__ csrc, int E, int N) {
    int i = blockIdx.x * blockDim.x + threadIdx.x;
    int e = i * 4;
    if (e + 3 < E) {
        int4 s4 = *reinterpret_cast<const int4*>(&src[e]);
        int4 d4 = *reinterpret_cast<const int4*>(&dst[e]);
        if (d4.x >= 0 && d4.x < N) csrc[atomicAdd(&cursor[d4.x], 1)] = s4.x;
        if (d4.y >= 0 && d4.y < N) csrc[atomicAdd(&cursor[d4.y], 1)] = s4.y;
        if (d4.z >= 0 && d4.z < N) csrc[atomicAdd(&cursor[d4.z], 1)] = s4.z;
        if (d4.w >= 0 && d4.w < N) csrc[atomicAdd(&cursor[d4.w], 1)] = s4.w;
    } else {
        for (int k = e; k < E; k++) {
            int d = dst[k];
            if (d >= 0 && d < N) csrc[atomicAdd(&cursor[d], 1)] = src[k];
        }
    }
}

// ---------------- aggregation (gather over CSR, warp per node) ----------------
// max over relu'd features (>=0, so init 0 matches reference incl. isolated nodes).
// Half-warp per edge-row: 16 lanes x float4 = full 256B row in one LDG.128.
__global__ void k_agg_max64(const float4* __restrict__ feat4, float4* __restrict__ out4,
                            const int* __restrict__ rowptr, const int* __restrict__ srcs,
                            int n) {
    int v = blockIdx.x * (blockDim.x >> 5) + (threadIdx.x >> 5);
    if (v >= n) return;
    int lane = threadIdx.x & 31;
    int half = lane >> 4, sub = lane & 15;
    int beg = rowptr[v], end = rowptr[v + 1];
    float4 a = make_float4(0.f, 0.f, 0.f, 0.f);
#pragma unroll 2
    for (int e = beg + half; e < end; e += 2) {
        int s = __ldg(&srcs[e]);
        float4 t = feat4[(size_t)s * 16 + sub];
        a.x = fmaxf(a.x, t.x);
        a.y = fmaxf(a.y, t.y);
        a.z = fmaxf(a.z, t.z);
        a.w = fmaxf(a.w, t.w);
    }
    a.x = fmaxf(a.x, __shfl_xor_sync(0xffffffffu, a.x, 16));
    a.y = fmaxf(a.y, __shfl_xor_sync(0xffffffffu, a.y, 16));
    a.z = fmaxf(a.z, __shfl_xor_sync(0xffffffffu, a.z, 16));
    a.w = fmaxf(a.w, __shfl_xor_sync(0xffffffffu, a.w, 16));
    if (half == 0) out4[(size_t)v * 16 + sub] = a;
}

// mean over 32-dim features. Quarter-warp per edge-row: 8 lanes x float4 = 128B row.
__global__ void k_agg_mean32(const float4* __restrict__ feat4, float4* __restrict__ out4,
                             const int* __restrict__ rowptr, const int* __restrict__ srcs,
                             int n) {
    int v = blockIdx.x * (blockDim.x >> 5) + (threadIdx.x >> 5);
    if (v >= n) return;
    int lane = threadIdx.x & 31;
    int q = lane >> 3, sub = lane & 7;
    int beg = rowptr[v], end = rowptr[v + 1];
    float4 a = make_float4(0.f, 0.f, 0.f, 0.f);
#pragma unroll 2
    for (int e = beg + q; e < end; e += 4) {
        int s = __ldg(&srcs[e]);
        float4 t = feat4[(size_t)s * 8 + sub];
        a.x += t.x; a.y += t.y; a.z += t.z; a.w += t.w;
    }
#pragma unroll
    for (int off = 8; off <= 16; off <<= 1) {
        a.x += __shfl_xor_sync(0xffffffffu, a.x, off);
        a.y += __shfl_xor_sync(0xffffffffu, a.y, off);
        a.z += __shfl_xor_sync(0xffffffffu, a.z, off);
        a.w += __shfl_xor_sync(0xffffffffu, a.w, off);
    }
    if (q == 0) {
        float cnt = (float)(end - beg);
        float inv = 1.f / fmaxf(cnt, 1.f);
        a.x *= inv; a.y *= inv; a.z *= inv; a.w *= inv;
        out4[(size_t)v * 8 + sub] = a;
    }
}

// ---------------- fused node GEMM (f32x2, k-quad, skewed smem) ----------------
// out = [relu]( A@W1 [+ B@W2] + bias ).  256 threads, 256 nodes/block,
// 8 nodes x TJ outs per thread.  A-tile rows skewed 16B per 8-row group so the
// 4 ng-groups of a warp hit distinct banks on float4 activation loads.
template <int IN, int OUT, bool RELU, bool TWO>
__global__ void __launch_bounds__(256) k_gemm(const float* __restrict__ A,
                                              const float* __restrict__ W1,
                                              const float* __restrict__ B,
                                              const float* __restrict__ W2,
                                              const float* __restrict__ bias,
                                              float* __restrict__ out, int n) {
    constexpr int NPB = 256;
    constexpr int TJ = OUT / 8;
    constexpr int NP = TJ / 2;
    constexpr int V = IN / 4;        // float4s per row
    extern __shared__ float sm[];
    float* sW1 = sm;                                // IN*OUT
    float* sW2 = TWO ? (sm + IN * OUT) : nullptr;   // IN*OUT
    float* sB = sm + IN * OUT * (TWO ? 2 : 1);      // OUT
    float* sA = sB + OUT;                           // NPB*IN + (NPB/8)*4

    auto rowoff = [](int nn) { return nn * IN + (nn >> 3) * 4; };

    int tid = threadIdx.x;
    for (int i = tid; i < IN * OUT; i += 256) {
        sW1[i] = W1[i];
        if (TWO) sW2[i] = W2[i];
    }
    for (int i = tid; i < OUT; i += 256) sB[i] = bias[i];

    int base = blockIdx.x * NPB;
    for (int i = tid; i < NPB * V; i += 256) {
        int nn = i / V, kk = (i % V) * 4;
        float4 v = make_float4(0.f, 0.f, 0.f, 0.f);
        if (base + nn < n)
            v = *reinterpret_cast<const float4*>(&A[(size_t)(base + nn) * IN + kk]);
        *reinterpret_cast<float4*>(&sA[rowoff(nn) + kk]) = v;
    }
    __syncthreads();

    int jg = tid & 7;
    int ng = tid >> 3;
    unsigned long long acc2[8][NP];
#pragma unroll
    for (int i = 0; i < 8; i++)
#pragma unroll
        for (int j = 0; j < NP; j++) acc2[i][j] = 0ull;

    int r0 = rowoff(ng * 8);  // 8 rows of one group: stride IN, no intra-group skew
    {
        const float* sW = sW1;
        for (int kq = 0; kq < IN; kq += 4) {
            float4 xv[8];
#pragma unroll
            for (int i = 0; i < 8; i++)
                xv[i] = *reinterpret_cast<const float4*>(&sA[r0 + i * IN + kq]);
#pragma unroll
            for (int h = 0; h < 2; h++) {       // half-quad: 2 ks at a time
                unsigned long long wv0[NP], wv1[NP];
#pragma unroll
                for (int p = 0; p < NP; p += 2) {
                    float4 w = *reinterpret_cast<const float4*>(
                        &sW[(kq + 2 * h) * OUT + jg * TJ + 2 * p]);
                    wv0[p] = pk2(w.x, w.y);
                    if (p + 1 < NP) wv0[p + 1] = pk2(w.z, w.w);
                }
#pragma unroll
                for (int p = 0; p < NP; p += 2) {
                    float4 w = *reinterpret_cast<const float4*>(
                        &sW[(kq + 2 * h + 1) * OUT + jg * TJ + 2 * p]);
                    wv1[p] = pk2(w.x, w.y);
                    if (p + 1 < NP) wv1[p + 1] = pk2(w.z, w.w);
                }
#pragma unroll
                for (int i = 0; i < 8; i++) {
                    float xlo = h ? xv[i].z : xv[i].x;
                    float xhi = h ? xv[i].w : xv[i].y;
                    unsigned long long a0 = pk2(xlo, xlo);
                    unsigned long long a1 = pk2(xhi, xhi);
#pragma unroll
                    for (int j = 0; j < NP; j++) {
                        fma2(acc2[i][j], a0, wv0[j]);
                        fma2(acc2[i][j], a1, wv1[j]);
                    }
                }
            }
        }
    }

    if (TWO) {
        __syncthreads();
        for (int i = tid; i < NPB * V; i += 256) {
            int nn = i / V, kk = (i % V) * 4;
            float4 v = make_float4(0.f, 0.f, 0.f, 0.f);
            if (base + nn < n)
                v = *reinterpret_cast<const float4*>(&B[(size_t)(base + nn) * IN + kk]);
            *reinterpret_cast<float4*>(&sA[rowoff(nn) + kk]) = v;
        }
        __syncthreads();
        const float* sW = sW2;
        for (int kq = 0; kq < IN; kq += 4) {
            float4 xv[8];
#pragma unroll
            for (int i = 0; i < 8; i++)
                xv[i] = *reinterpret_cast<const float4*>(&sA[r0 + i * IN + kq]);
#pragma unroll
            for (int h = 0; h < 2; h++) {
                unsigned long long wv0[NP], wv1[NP];
#pragma unroll
                for (int p = 0; p < NP; p += 2) {
                    float4 w = *reinterpret_cast<const float4*>(
                        &sW[(kq + 2 * h) * OUT + jg * TJ + 2 * p]);
                    wv0[p] = pk2(w.x, w.y);
                    if (p + 1 < NP) wv0[p + 1] = pk2(w.z, w.w);
                }
#pragma unroll
                for (int p = 0; p < NP; p += 2) {
                    float4 w = *reinterpret_cast<const float4*>(
                        &sW[(kq + 2 * h + 1) * OUT + jg * TJ + 2 * p]);
                    wv1[p] = pk2(w.x, w.y);
                    if (p + 1 < NP) wv1[p + 1] = pk2(w.z, w.w);
                }
#pragma unroll
                for (int i = 0; i < 8; i++) {
                    float xlo = h ? xv[i].z : xv[i].x;
                    float xhi = h ? xv[i].w : xv[i].y;
                    unsigned long long a0 = pk2(xlo, xlo);
                    unsigned long long a1 = pk2(xhi, xhi);
#pragma unroll
                    for (int j = 0; j < NP; j++) {
                        fma2(acc2[i][j], a0, wv0[j]);
                        fma2(acc2[i][j], a1, wv1[j]);
                    }
                }
            }
        }
    }

#pragma unroll
    for (int i = 0; i < 8; i++) {
        int node = base + ng * 8 + i;
        if (node < n) {
#pragma unroll
            for (int j = 0; j < NP; j++) {
                float lo, hi;
                upk2(acc2[i][j], lo, hi);
                float v0 = lo + sB[jg * TJ + 2 * j];
                float v1 = hi + sB[jg * TJ + 2 * j + 1];
                if (RELU) { v0 = fmaxf(v0, 0.f); v1 = fmaxf(v1, 0.f); }
                out[(size_t)node * OUT + jg * TJ + 2 * j] = v0;
                out[(size_t)node * OUT + jg * TJ + 2 * j + 1] = v1;
            }
        }
    }
}

// ---------------- host launch ----------------
static inline int smem_bytes(int IN, int OUT, bool TWO) {
    return (IN * OUT * (TWO ? 2 : 1) + OUT + 256 * IN + 32 * 4) * (int)sizeof(float);
}

extern "C" void kernel_launch(void* const* d_in, const int* in_sizes, int n_in,
                              void* d_out, int out_size) {
    const float* x        = (const float*)d_in[0];
    const int*   ei       = (const int*)d_in[1];   // int32 (JAX x64 disabled)
    const float* W1_pool  = (const float*)d_in[2];
    const float* b1_pool  = (const float*)d_in[3];
    const float* W1_self  = (const float*)d_in[4];
    const float* W1_neigh = (const float*)d_in[5];
    const float* b1       = (const float*)d_in[6];
    const float* W2_pool  = (const float*)d_in[7];
    const float* b2_pool  = (const float*)d_in[8];
    const float* W2_self  = (const float*)d_in[9];
    const float* W2_neigh = (const float*)d_in[10];
    const float* b2       = (const float*)d_in[11];
    const float* W3_self  = (const float*)d_in[12];
    const float* W3_neigh = (const float*)d_in[13];
    const float* b3       = (const float*)d_in[14];

    int N = in_sizes[0] / 64;
    int E = in_sizes[1] / 2;
    if (N > MAXN) N = MAXN;
    if (E > MAXE) E = MAXE;

    const int* src = ei;        // row 0
    const int* dst = ei + E;    // row 1

    float *m, *agg, *h1, *h2, *agg3;
    int *rowptr, *deg, *csrc;
    cudaGetSymbolAddress((void**)&m, g_m);
    cudaGetSymbolAddress((void**)&agg, g_agg);
    cudaGetSymbolAddress((void**)&h1, g_h1);
    cudaGetSymbolAddress((void**)&h2, g_h2);
    cudaGetSymbolAddress((void**)&agg3, g_agg3);
    cudaGetSymbolAddress((void**)&rowptr, g_rowptr);
    cudaGetSymbolAddress((void**)&deg, g_deg);
    cudaGetSymbolAddress((void**)&csrc, g_csrc);

    cudaFuncSetAttribute((const void*)k_gemm<64, 64, true, false>,
                         cudaFuncAttributeMaxDynamicSharedMemorySize, smem_bytes(64, 64, false));
    cudaFuncSetAttribute((const void*)k_gemm<64, 64, true, true>,
                         cudaFuncAttributeMaxDynamicSharedMemorySize, smem_bytes(64, 64, true));
    cudaFuncSetAttribute((const void*)k_gemm<64, 32, false, true>,
                         cudaFuncAttributeMaxDynamicSharedMemorySize, smem_bytes(64, 32, true));
    cudaFuncSetAttribute((const void*)k_gemm<32, 32, false, true>,
                         cudaFuncAttributeMaxDynamicSharedMemorySize, smem_bytes(32, 32, true));

    int e4blocks = ((E + 3) / 4 + 255) / 256;
    int nblocks256 = (N + 255) / 256;
    int aggBlocks = (N + 7) / 8;  // 8 warps / block

    // ---- CSR build ----
    cudaMemsetAsync(deg, 0, (size_t)N * sizeof(int));
    k_hist<<<e4blocks, 256>>>(dst, deg, E, N);
    k_scanfused<<<1, 1024>>>(deg, rowptr, deg, N, E);  // deg becomes cursor
    k_scatter<<<e4blocks, 256>>>(src, dst, deg, csrc, E, N);

    // ---- layer 1 (pool) ----
    k_gemm<64, 64, true, false><<<nblocks256, 256, smem_bytes(64, 64, false)>>>(
        x, W1_pool, nullptr, nullptr, b1_pool, m, N);
    k_agg_max64<<<aggBlocks, 256>>>((const float4*)m, (float4*)agg, rowptr, csrc, N);
    k_gemm<64, 64, true, true><<<nblocks256, 256, smem_bytes(64, 64, true)>>>(
        x, W1_self, agg, W1_neigh, b1, h1, N);

    // ---- layer 2 (pool) ----
    k_gemm<64, 64, true, false><<<nblocks256, 256, smem_bytes(64, 64, false)>>>(
        h1, W2_pool, nullptr, nullptr, b2_pool, m, N);
    k_agg_max64<<<aggBlocks, 256>>>((const float4*)m, (float4*)agg, rowptr, csrc, N);
    k_gemm<64, 32, false, true><<<nblocks256, 256, smem_bytes(64, 32, true)>>>(
        h1, W2_self, agg, W2_neigh, b2, h2, N);

    // ---- layer 3 (mean) ----
    k_agg_mean32<<<aggBlocks, 256>>>((const float4*)h2, (float4*)agg3, rowptr, csrc, N);
    k_gemm<32, 32, false, true><<<nblocks256, 256, smem_bytes(32, 32, true)>>>(
        h2, W3_self, agg3, W3_neigh, b3, (float*)d_out, N);
}

// round 9
// speedup vs baseline: 1.4589x; 1.3884x over previous
#include <cuda_runtime.h>
#include <cstdint>

#define MAXN 100000
#define MAXE 1600000

// ---------------- scratch (device globals; no allocs allowed) ----------------
__device__ float g_m[MAXN * 64];      // pool-transformed features
__device__ float g_agg[MAXN * 64];    // aggregated features
__device__ float g_h1[MAXN * 64];     // layer-1 output
__device__ float g_h2[MAXN * 32];     // layer-2 output
__device__ float g_agg3[MAXN * 32];   // layer-3 mean aggregate
__device__ int   g_rowptr[MAXN + 1];
__device__ int   g_deg[MAXN];         // degree, then reused as scatter cursor
__device__ int   g_scantmp[MAXN];
__device__ int   g_bsum[1024];
__device__ int   g_csrc[MAXE];        // CSR src ids, grouped by dst

// ---------------- f32x2 packed-FMA helpers (sm_100+) ----------------
__device__ __forceinline__ unsigned long long pk2(float lo, float hi) {
    unsigned long long r;
    asm("mov.b64 %0,{%1,%2};" : "=l"(r) : "f"(lo), "f"(hi));
    return r;
}
__device__ __forceinline__ void fma2(unsigned long long& d, unsigned long long a,
                                     unsigned long long b) {
    asm("fma.rn.f32x2 %0, %1, %2, %0;" : "+l"(d) : "l"(a), "l"(b));
}
__device__ __forceinline__ void upk2(unsigned long long v, float& lo, float& hi) {
    asm("mov.b64 {%0,%1},%2;" : "=f"(lo), "=f"(hi) : "l"(v));
}

// ---------------- CSR build ----------------
__global__ void k_hist(const int* __restrict__ dst, int* __restrict__ deg, int E, int N) {
    int i = blockIdx.x * blockDim.x + threadIdx.x;
    int e = i * 4;
    if (e + 3 < E) {
        int4 d4 = *reinterpret_cast<const int4*>(&dst[e]);
        if (d4.x >= 0 && d4.x < N) atomicAdd(&deg[d4.x], 1);
        if (d4.y >= 0 && d4.y < N) atomicAdd(&deg[d4.y], 1);
        if (d4.z >= 0 && d4.z < N) atomicAdd(&deg[d4.z], 1);
        if (d4.w >= 0 && d4.w < N) atomicAdd(&deg[d4.w], 1);
    } else {
        for (int k = e; k < E; k++) {
            int d = dst[k];
            if (d >= 0 && d < N) atomicAdd(&deg[d], 1);
        }
    }
}

// pass 1: per-block inclusive scan (512 elems / block)
__global__ void k_scan1(const int* __restrict__ deg, int* __restrict__ scantmp,
                        int* __restrict__ bsum, int n) {
    __shared__ int sh[512];
    int tid = threadIdx.x;
    int i = blockIdx.x * 512 + tid;
    int v = (i < n) ? deg[i] : 0;
    sh[tid] = v;
    __syncthreads();
#pragma unroll
    for (int off = 1; off < 512; off <<= 1) {
        int t = (tid >= off) ? sh[tid - off] : 0;
        __syncthreads();
        sh[tid] += t;
        __syncthreads();
    }
    if (i < n) scantmp[i] = sh[tid];
    if (tid == 511) bsum[blockIdx.x] = sh[511];
}

// pass 2: parallel exclusive scan of block sums (nb <= 256)
__global__ void k_scan2(int* bsum, int nb) {
    __shared__ int sh[256];
    int tid = threadIdx.x;
    int v = (tid < nb) ? bsum[tid] : 0;
    sh[tid] = v;
    __syncthreads();
#pragma unroll
    for (int off = 1; off < 256; off <<= 1) {
        int t = (tid >= off) ? sh[tid - off] : 0;
        __syncthreads();
        sh[tid] += t;
        __syncthreads();
    }
    if (tid < nb) bsum[tid] = sh[tid] - v;  // exclusive
}

// pass 3: exclusive rowptr + cursor init (deg array becomes cursor)
__global__ void k_scan3(const int* __restrict__ scantmp, int* __restrict__ deg_cursor,
                        int* __restrict__ rowptr, const int* __restrict__ bsum,
                        int n, int E) {
    int i = blockIdx.x * blockDim.x + threadIdx.x;
    if (i < n) {
        int d = deg_cursor[i];
        int ex = scantmp[i] - d + bsum[i >> 9];
        rowptr[i] = ex;
        deg_cursor[i] = ex;   // cursor
    }
    if (i == 0) rowptr[n] = E;
}

__global__ void k_scatter(const int* __restrict__ src, const int* __restrict__ dst,
                          int* __restrict__ cursor, int* __restrict__ csrc, int E, int N) {
    int i = blockIdx.x * blockDim.x + threadIdx.x;
    int e = i * 4;
    if (e + 3 < E) {
        int4 s4 = *reinterpret_cast<const int4*>(&src[e]);
        int4 d4 = *reinterpret_cast<const int4*>(&dst[e]);
        if (d4.x >= 0 && d4.x < N) csrc[atomicAdd(&cursor[d4.x], 1)] = s4.x;
        if (d4.y >= 0 && d4.y < N) csrc[atomicAdd(&cursor[d4.y], 1)] = s4.y;
        if (d4.z >= 0 && d4.z < N) csrc[atomicAdd(&cursor[d4.z], 1)] = s4.z;
        if (d4.w >= 0 && d4.w < N) csrc[atomicAdd(&cursor[d4.w], 1)] = s4.w;
    } else {
        for (int k = e; k < E; k++) {
            int d = dst[k];
            if (d >= 0 && d < N) csrc[atomicAdd(&cursor[d], 1)] = src[k];
        }
    }
}

// ---------------- aggregation (gather over CSR, warp per node) ----------------
// max over relu'd features (>=0, so init 0 matches reference incl. isolated nodes).
// Half-warp per edge-row: 16 lanes x float4 = full 256B row in one LDG.128.
__global__ void k_agg_max64(const float4* __restrict__ feat4, float4* __restrict__ out4,
                            const int* __restrict__ rowptr, const int* __restrict__ srcs,
                            int n) {
    int v = blockIdx.x * (blockDim.x >> 5) + (threadIdx.x >> 5);
    if (v >= n) return;
    int lane = threadIdx.x & 31;
    int half = lane >> 4, sub = lane & 15;
    int beg = rowptr[v], end = rowptr[v + 1];
    float4 a = make_float4(0.f, 0.f, 0.f, 0.f);
#pragma unroll 2
    for (int e = beg + half; e < end; e += 2) {
        int s = __ldg(&srcs[e]);
        float4 t = feat4[(size_t)s * 16 + sub];
        a.x = fmaxf(a.x, t.x);
        a.y = fmaxf(a.y, t.y);
        a.z = fmaxf(a.z, t.z);
        a.w = fmaxf(a.w, t.w);
    }
    a.x = fmaxf(a.x, __shfl_xor_sync(0xffffffffu, a.x, 16));
    a.y = fmaxf(a.y, __shfl_xor_sync(0xffffffffu, a.y, 16));
    a.z = fmaxf(a.z, __shfl_xor_sync(0xffffffffu, a.z, 16));
    a.w = fmaxf(a.w, __shfl_xor_sync(0xffffffffu, a.w, 16));
    if (half == 0) out4[(size_t)v * 16 + sub] = a;
}

// mean over 32-dim features. Quarter-warp per edge-row: 8 lanes x float4 = 128B row.
__global__ void k_agg_mean32(const float4* __restrict__ feat4, float4* __restrict__ out4,
                             const int* __restrict__ rowptr, const int* __restrict__ srcs,
                             int n) {
    int v = blockIdx.x * (blockDim.x >> 5) + (threadIdx.x >> 5);
    if (v >= n) return;
    int lane = threadIdx.x & 31;
    int q = lane >> 3, sub = lane & 7;
    int beg = rowptr[v], end = rowptr[v + 1];
    float4 a = make_float4(0.f, 0.f, 0.f, 0.f);
#pragma unroll 2
    for (int e = beg + q; e < end; e += 4) {
        int s = __ldg(&srcs[e]);
        float4 t = feat4[(size_t)s * 8 + sub];
        a.x += t.x; a.y += t.y; a.z += t.z; a.w += t.w;
    }
#pragma unroll
    for (int off = 8; off <= 16; off <<= 1) {
        a.x += __shfl_xor_sync(0xffffffffu, a.x, off);
        a.y += __shfl_xor_sync(0xffffffffu, a.y, off);
        a.z += __shfl_xor_sync(0xffffffffu, a.z, off);
        a.w += __shfl_xor_sync(0xffffffffu, a.w, off);
    }
    if (q == 0) {
        float cnt = (float)(end - beg);
        float inv = 1.f / fmaxf(cnt, 1.f);
        a.x *= inv; a.y *= inv; a.z *= inv; a.w *= inv;
        out4[(size_t)v * 8 + sub] = a;
    }
}

// ---------------- node GEMM: direct-LDG activations, weights-only smem ----------------
// out = [relu]( A@W1 [+ B@W2] + bias ).  256 threads, 128 nodes/block,
// per-thread tile: 4 nodes x TJ outs.  Activations read straight from global as
// float4 (8 jg-threads share each row -> same-address broadcast, L1-resident).
template <int IN, int OUT, bool RELU, bool TWO>
__global__ void __launch_bounds__(256) k_gemm(const float4* __restrict__ A4,
                                              const float* __restrict__ W1,
                                              const float4* __restrict__ B4,
                                              const float* __restrict__ W2,
                                              const float* __restrict__ bias,
                                              float* __restrict__ out, int n) {
    constexpr int NPB = 128;
    constexpr int TJ = OUT / 8;
    constexpr int NP = TJ / 2;
    constexpr int V = IN / 4;        // float4s per activation row
    extern __shared__ float sm[];
    float* sW1 = sm;                                // IN*OUT
    float* sW2 = TWO ? (sm + IN * OUT) : nullptr;   // IN*OUT
    float* sB = sm + IN * OUT * (TWO ? 2 : 1);      // OUT

    int tid = threadIdx.x;
    for (int i = tid; i < IN * OUT; i += 256) {
        sW1[i] = W1[i];
        if (TWO) sW2[i] = W2[i];
    }
    for (int i = tid; i < OUT; i += 256) sB[i] = bias[i];
    __syncthreads();

    int jg = tid & 7;
    int ng = tid >> 3;                 // 0..31, each owns 4 nodes
    int base = blockIdx.x * NPB;
    int n0 = base + ng * 4;            // first node of this thread

    unsigned long long acc2[4][NP];
#pragma unroll
    for (int i = 0; i < 4; i++)
#pragma unroll
        for (int j = 0; j < NP; j++) acc2[i][j] = 0ull;

    {
        const float* sW = sW1;
        for (int kq = 0; kq < IN; kq += 4) {
            float4 xv[4];
#pragma unroll
            for (int i = 0; i < 4; i++)
                xv[i] = (n0 + i < n) ? __ldg(&A4[(size_t)(n0 + i) * V + (kq >> 2)])
                                     : make_float4(0.f, 0.f, 0.f, 0.f);
#pragma unroll
            for (int h = 0; h < 2; h++) {       // 2 ks per half-quad
                unsigned long long wv0[NP], wv1[NP];
#pragma unroll
                for (int p = 0; p < NP; p += 2) {
                    float4 w = *reinterpret_cast<const float4*>(
                        &sW[(kq + 2 * h) * OUT + jg * TJ + 2 * p]);
                    wv0[p] = pk2(w.x, w.y);
                    if (p + 1 < NP) wv0[p + 1] = pk2(w.z, w.w);
                }
#pragma unroll
                for (int p = 0; p < NP; p += 2) {
                    float4 w = *reinterpret_cast<const float4*>(
                        &sW[(kq + 2 * h + 1) * OUT + jg * TJ + 2 * p]);
                    wv1[p] = pk2(w.x, w.y);
                    if (p + 1 < NP) wv1[p + 1] = pk2(w.z, w.w);
                }
#pragma unroll
                for (int i = 0; i < 4; i++) {
                    float xlo = h ? xv[i].z : xv[i].x;
                    float xhi = h ? xv[i].w : xv[i].y;
                    unsigned long long a0 = pk2(xlo, xlo);
                    unsigned long long a1 = pk2(xhi, xhi);
#pragma unroll
                    for (int j = 0; j < NP; j++) {
                        fma2(acc2[i][j], a0, wv0[j]);
                        fma2(acc2[i][j], a1, wv1[j]);
                    }
                }
            }
        }
    }

    if (TWO) {
        const float* sW = sW2;
        for (int kq = 0; kq < IN; kq += 4) {
            float4 xv[4];
#pragma unroll
            for (int i = 0; i < 4; i++)
                xv[i] = (n0 + i < n) ? __ldg(&B4[(size_t)(n0 + i) * V + (kq >> 2)])
                                     : make_float4(0.f, 0.f, 0.f, 0.f);
#pragma unroll
            for (int h = 0; h < 2; h++) {
                unsigned long long wv0[NP], wv1[NP];
#pragma unroll
                for (int p = 0; p < NP; p += 2) {
                    float4 w = *reinterpret_cast<const float4*>(
                        &sW[(kq + 2 * h) * OUT + jg * TJ + 2 * p]);
                    wv0[p] = pk2(w.x, w.y);
                    if (p + 1 < NP) wv0[p + 1] = pk2(w.z, w.w);
                }
#pragma unroll
                for (int p = 0; p < NP; p += 2) {
                    float4 w = *reinterpret_cast<const float4*>(
                        &sW[(kq + 2 * h + 1) * OUT + jg * TJ + 2 * p]);
                    wv1[p] = pk2(w.x, w.y);
                    if (p + 1 < NP) wv1[p + 1] = pk2(w.z, w.w);
                }
#pragma unroll
                for (int i = 0; i < 4; i++) {
                    float xlo = h ? xv[i].z : xv[i].x;
                    float xhi = h ? xv[i].w : xv[i].y;
                    unsigned long long a0 = pk2(xlo, xlo);
                    unsigned long long a1 = pk2(xhi, xhi);
#pragma unroll
                    for (int j = 0; j < NP; j++) {
                        fma2(acc2[i][j], a0, wv0[j]);
                        fma2(acc2[i][j], a1, wv1[j]);
                    }
                }
            }
        }
    }

#pragma unroll
    for (int i = 0; i < 4; i++) {
        int node = n0 + i;
        if (node < n) {
#pragma unroll
            for (int j = 0; j < NP; j++) {
                float lo, hi;
                upk2(acc2[i][j], lo, hi);
                float v0 = lo + sB[jg * TJ + 2 * j];
                float v1 = hi + sB[jg * TJ + 2 * j + 1];
                if (RELU) { v0 = fmaxf(v0, 0.f); v1 = fmaxf(v1, 0.f); }
                out[(size_t)node * OUT + jg * TJ + 2 * j] = v0;
                out[(size_t)node * OUT + jg * TJ + 2 * j + 1] = v1;
            }
        }
    }
}

// ---------------- host launch ----------------
static inline int smem_bytes(int IN, int OUT, bool TWO) {
    return (IN * OUT * (TWO ? 2 : 1) + OUT) * (int)sizeof(float);
}

extern "C" void kernel_launch(void* const* d_in, const int* in_sizes, int n_in,
                              void* d_out, int out_size) {
    const float* x        = (const float*)d_in[0];
    const int*   ei       = (const int*)d_in[1];   // int32 (JAX x64 disabled)
    const float* W1_pool  = (const float*)d_in[2];
    const float* b1_pool  = (const float*)d_in[3];
    const float* W1_self  = (const float*)d_in[4];
    const float* W1_neigh = (const float*)d_in[5];
    const float* b1       = (const float*)d_in[6];
    const float* W2_pool  = (const float*)d_in[7];
    const float* b2_pool  = (const float*)d_in[8];
    const float* W2_self  = (const float*)d_in[9];
    const float* W2_neigh = (const float*)d_in[10];
    const float* b2       = (const float*)d_in[11];
    const float* W3_self  = (const float*)d_in[12];
    const float* W3_neigh = (const float*)d_in[13];
    const float* b3       = (const float*)d_in[14];

    int N = in_sizes[0] / 64;
    int E = in_sizes[1] / 2;
    if (N > MAXN) N = MAXN;
    if (E > MAXE) E = MAXE;

    const int* src = ei;        // row 0
    const int* dst = ei + E;    // row 1

    float *m, *agg, *h1, *h2, *agg3;
    int *rowptr, *deg, *scantmp, *bsum, *csrc;
    cudaGetSymbolAddress((void**)&m, g_m);
    cudaGetSymbolAddress((void**)&agg, g_agg);
    cudaGetSymbolAddress((void**)&h1, g_h1);
    cudaGetSymbolAddress((void**)&h2, g_h2);
    cudaGetSymbolAddress((void**)&agg3, g_agg3);
    cudaGetSymbolAddress((void**)&rowptr, g_rowptr);
    cudaGetSymbolAddress((void**)&deg, g_deg);
    cudaGetSymbolAddress((void**)&scantmp, g_scantmp);
    cudaGetSymbolAddress((void**)&bsum, g_bsum);
    cudaGetSymbolAddress((void**)&csrc, g_csrc);

    int e4blocks = ((E + 3) / 4 + 255) / 256;
    int nblocks256 = (N + 255) / 256;
    int nblocks128 = (N + 127) / 128;
    int nbScan = (N + 511) / 512;
    int aggBlocks = (N + 7) / 8;  // 8 warps / block

    // ---- CSR build ----
    cudaMemsetAsync(deg, 0, (size_t)N * sizeof(int));
    k_hist<<<e4blocks, 256>>>(dst, deg, E, N);
    k_scan1<<<nbScan, 512>>>(deg, scantmp, bsum, N);
    k_scan2<<<1, 256>>>(bsum, nbScan);
    k_scan3<<<nblocks256, 256>>>(scantmp, deg, rowptr, bsum, N, E);
    k_scatter<<<e4blocks, 256>>>(src, dst, deg, csrc, E, N);

    // ---- layer 1 (pool) ----
    k_gemm<64, 64, true, false><<<nblocks128, 256, smem_bytes(64, 64, false)>>>(
        (const float4*)x, W1_pool, nullptr, nullptr, b1_pool, m, N);
    k_agg_max64<<<aggBlocks, 256>>>((const float4*)m, (float4*)agg, rowptr, csrc, N);
    k_gemm<64, 64, true, true><<<nblocks128, 256, smem_bytes(64, 64, true)>>>(
        (const float4*)x, W1_self, (const float4*)agg, W1_neigh, b1, h1, N);

    // ---- layer 2 (pool) ----
    k_gemm<64, 64, true, false><<<nblocks128, 256, smem_bytes(64, 64, false)>>>(
        (const float4*)h1, W2_pool, nullptr, nullptr, b2_pool, m, N);
    k_agg_max64<<<aggBlocks, 256>>>((const float4*)m, (float4*)agg, rowptr, csrc, N);
    k_gemm<64, 32, false, true><<<nblocks128, 256, smem_bytes(64, 32, true)>>>(
        (const float4*)h1, W2_self, (const float4*)agg, W2_neigh, b2, h2, N);

    // ---- layer 3 (mean) ----
    k_agg_mean32<<<aggBlocks, 256>>>((const float4*)h2, (float4*)agg3, rowptr, csrc, N);
    k_gemm<32, 32, false, true><<<nblocks128, 256, smem_bytes(32, 32, true)>>>(
        (const float4*)h2, W3_self, (const float4*)agg3, W3_neigh, b3, (float*)d_out, N);
}

// round 10
// speedup vs baseline: 1.5366x; 1.0532x over previous
#include <cuda_runtime.h>
#include <cstdint>

#define MAXN 100000
#define MAXE 1600000

// ---------------- scratch (device globals; no allocs allowed) ----------------
__device__ float g_m[MAXN * 64];      // pool-transformed features
__device__ float g_agg[MAXN * 64];    // aggregated features
__device__ float g_h1[MAXN * 64];     // layer-1 output
__device__ float g_h2[MAXN * 32];     // layer-2 output
__device__ float g_agg3[MAXN * 32];   // layer-3 mean aggregate
__device__ int   g_rowptr[MAXN + 1];
__device__ int   g_deg[MAXN];         // degree, then reused as scatter cursor
__device__ int   g_scantmp[MAXN];
__device__ int   g_bsum[1024];
__device__ int   g_csrc[MAXE];        // CSR src ids, grouped by dst

// ---------------- f32x2 packed-FMA helpers (sm_100+) ----------------
__device__ __forceinline__ unsigned long long pk2(float lo, float hi) {
    unsigned long long r;
    asm("mov.b64 %0,{%1,%2};" : "=l"(r) : "f"(lo), "f"(hi));
    return r;
}
__device__ __forceinline__ void fma2(unsigned long long& d, unsigned long long a,
                                     unsigned long long b) {
    asm("fma.rn.f32x2 %0, %1, %2, %0;" : "+l"(d) : "l"(a), "l"(b));
}
__device__ __forceinline__ void upk2(unsigned long long v, float& lo, float& hi) {
    asm("mov.b64 {%0,%1},%2;" : "=f"(lo), "=f"(hi) : "l"(v));
}

// ---------------- CSR build ----------------
__global__ void k_hist(const int* __restrict__ dst, int* __restrict__ deg, int E, int N) {
    int i = blockIdx.x * blockDim.x + threadIdx.x;
    int e = i * 4;
    if (e + 3 < E) {
        int4 d4 = *reinterpret_cast<const int4*>(&dst[e]);
        if (d4.x >= 0 && d4.x < N) atomicAdd(&deg[d4.x], 1);
        if (d4.y >= 0 && d4.y < N) atomicAdd(&deg[d4.y], 1);
        if (d4.z >= 0 && d4.z < N) atomicAdd(&deg[d4.z], 1);
        if (d4.w >= 0 && d4.w < N) atomicAdd(&deg[d4.w], 1);
    } else {
        for (int k = e; k < E; k++) {
            int d = dst[k];
            if (d >= 0 && d < N) atomicAdd(&deg[d], 1);
        }
    }
}

__global__ void k_scan1(const int* __restrict__ deg, int* __restrict__ scantmp,
                        int* __restrict__ bsum, int n) {
    __shared__ int sh[512];
    int tid = threadIdx.x;
    int i = blockIdx.x * 512 + tid;
    int v = (i < n) ? deg[i] : 0;
    sh[tid] = v;
    __syncthreads();
#pragma unroll
    for (int off = 1; off < 512; off <<= 1) {
        int t = (tid >= off) ? sh[tid - off] : 0;
        __syncthreads();
        sh[tid] += t;
        __syncthreads();
    }
    if (i < n) scantmp[i] = sh[tid];
    if (tid == 511) bsum[blockIdx.x] = sh[511];
}

__global__ void k_scan2(int* bsum, int nb) {
    __shared__ int sh[256];
    int tid = threadIdx.x;
    int v = (tid < nb) ? bsum[tid] : 0;
    sh[tid] = v;
    __syncthreads();
#pragma unroll
    for (int off = 1; off < 256; off <<= 1) {
        int t = (tid >= off) ? sh[tid - off] : 0;
        __syncthreads();
        sh[tid] += t;
        __syncthreads();
    }
    if (tid < nb) bsum[tid] = sh[tid] - v;  // exclusive
}

__global__ void k_scan3(const int* __restrict__ scantmp, int* __restrict__ deg_cursor,
                        int* __restrict__ rowptr, const int* __restrict__ bsum,
                        int n, int E) {
    int i = blockIdx.x * blockDim.x + threadIdx.x;
    if (i < n) {
        int d = deg_cursor[i];
        int ex = scantmp[i] - d + bsum[i >> 9];
        rowptr[i] = ex;
        deg_cursor[i] = ex;   // cursor
    }
    if (i == 0) rowptr[n] = E;
}

__global__ void k_scatter(const int* __restrict__ src, const int* __restrict__ dst,
                          int* __restrict__ cursor, int* __restrict__ csrc, int E, int N) {
    int i = blockIdx.x * blockDim.x + threadIdx.x;
    int e = i * 4;
    if (e + 3 < E) {
        int4 s4 = *reinterpret_cast<const int4*>(&src[e]);
        int4 d4 = *reinterpret_cast<const int4*>(&dst[e]);
        if (d4.x >= 0 && d4.x < N) csrc[atomicAdd(&cursor[d4.x], 1)] = s4.x;
        if (d4.y >= 0 && d4.y < N) csrc[atomicAdd(&cursor[d4.y], 1)] = s4.y;
        if (d4.z >= 0 && d4.z < N) csrc[atomicAdd(&cursor[d4.z], 1)] = s4.z;
        if (d4.w >= 0 && d4.w < N) csrc[atomicAdd(&cursor[d4.w], 1)] = s4.w;
    } else {
        for (int k = e; k < E; k++) {
            int d = dst[k];
            if (d >= 0 && d < N) csrc[atomicAdd(&cursor[d], 1)] = src[k];
        }
    }
}

// ---------------- aggregation (gather over CSR, warp per node) ----------------
__global__ void k_agg_max64(const float4* __restrict__ feat4, float4* __restrict__ out4,
                            const int* __restrict__ rowptr, const int* __restrict__ srcs,
                            int n) {
    int v = blockIdx.x * (blockDim.x >> 5) + (threadIdx.x >> 5);
    if (v >= n) return;
    int lane = threadIdx.x & 31;
    int half = lane >> 4, sub = lane & 15;
    int beg = rowptr[v], end = rowptr[v + 1];
    float4 a = make_float4(0.f, 0.f, 0.f, 0.f);
#pragma unroll 2
    for (int e = beg + half; e < end; e += 2) {
        int s = __ldg(&srcs[e]);
        float4 t = feat4[(size_t)s * 16 + sub];
        a.x = fmaxf(a.x, t.x);
        a.y = fmaxf(a.y, t.y);
        a.z = fmaxf(a.z, t.z);
        a.w = fmaxf(a.w, t.w);
    }
    a.x = fmaxf(a.x, __shfl_xor_sync(0xffffffffu, a.x, 16));
    a.y = fmaxf(a.y, __shfl_xor_sync(0xffffffffu, a.y, 16));
    a.z = fmaxf(a.z, __shfl_xor_sync(0xffffffffu, a.z, 16));
    a.w = fmaxf(a.w, __shfl_xor_sync(0xffffffffu, a.w, 16));
    if (half == 0) out4[(size_t)v * 16 + sub] = a;
}

__global__ void k_agg_mean32(const float4* __restrict__ feat4, float4* __restrict__ out4,
                             const int* __restrict__ rowptr, const int* __restrict__ srcs,
                             int n) {
    int v = blockIdx.x * (blockDim.x >> 5) + (threadIdx.x >> 5);
    if (v >= n) return;
    int lane = threadIdx.x & 31;
    int q = lane >> 3, sub = lane & 7;
    int beg = rowptr[v], end = rowptr[v + 1];
    float4 a = make_float4(0.f, 0.f, 0.f, 0.f);
#pragma unroll 2
    for (int e = beg + q; e < end; e += 4) {
        int s = __ldg(&srcs[e]);
        float4 t = feat4[(size_t)s * 8 + sub];
        a.x += t.x; a.y += t.y; a.z += t.z; a.w += t.w;
    }
#pragma unroll
    for (int off = 8; off <= 16; off <<= 1) {
        a.x += __shfl_xor_sync(0xffffffffu, a.x, off);
        a.y += __shfl_xor_sync(0xffffffffu, a.y, off);
        a.z += __shfl_xor_sync(0xffffffffu, a.z, off);
        a.w += __shfl_xor_sync(0xffffffffu, a.w, off);
    }
    if (q == 0) {
        float cnt = (float)(end - beg);
        float inv = 1.f / fmaxf(cnt, 1.f);
        a.x *= inv; a.y *= inv; a.z *= inv; a.w *= inv;
        out4[(size_t)v * 8 + sub] = a;
    }
}

// ---------------- node GEMM: direct-LDG activations, weights-only smem ----------------
// !ADD: out = [relu]( A@W + bias )
//  ADD: out = [relu]( out + A@W )          (bias unused)
// 256 threads, 128 nodes/block, 4 nodes x TJ outs per thread.
template <int IN, int OUT, bool RELU, bool ADD>
__global__ void __launch_bounds__(256, 3) k_gemm(const float4* __restrict__ A4,
                                                 const float* __restrict__ W,
                                                 const float* __restrict__ bias,
                                                 float* __restrict__ out, int n) {
    constexpr int NPB = 128;
    constexpr int TJ = OUT / 8;
    constexpr int NP = TJ / 2;
    constexpr int V = IN / 4;
    extern __shared__ float sm[];
    float* sW = sm;              // IN*OUT
    float* sB = sm + IN * OUT;   // OUT

    int tid = threadIdx.x;
    for (int i = tid; i < IN * OUT; i += 256) sW[i] = W[i];
    if (!ADD)
        for (int i = tid; i < OUT; i += 256) sB[i] = bias[i];
    __syncthreads();

    int jg = tid & 7;
    int ng = tid >> 3;
    int base = blockIdx.x * NPB;
    int n0 = base + ng * 4;

    unsigned long long acc2[4][NP];
#pragma unroll
    for (int i = 0; i < 4; i++)
#pragma unroll
        for (int j = 0; j < NP; j++) acc2[i][j] = 0ull;

    for (int kq = 0; kq < IN; kq += 4) {
        float4 xv[4];
#pragma unroll
        for (int i = 0; i < 4; i++)
            xv[i] = (n0 + i < n) ? __ldg(&A4[(size_t)(n0 + i) * V + (kq >> 2)])
                                 : make_float4(0.f, 0.f, 0.f, 0.f);
#pragma unroll
        for (int h = 0; h < 2; h++) {
            unsigned long long wv0[NP], wv1[NP];
#pragma unroll
            for (int p = 0; p < NP; p += 2) {
                float4 w = *reinterpret_cast<const float4*>(
                    &sW[(kq + 2 * h) * OUT + jg * TJ + 2 * p]);
                wv0[p] = pk2(w.x, w.y);
                if (p + 1 < NP) wv0[p + 1] = pk2(w.z, w.w);
            }
#pragma unroll
            for (int p = 0; p < NP; p += 2) {
                float4 w = *reinterpret_cast<const float4*>(
                    &sW[(kq + 2 * h + 1) * OUT + jg * TJ + 2 * p]);
                wv1[p] = pk2(w.x, w.y);
                if (p + 1 < NP) wv1[p + 1] = pk2(w.z, w.w);
            }
#pragma unroll
            for (int i = 0; i < 4; i++) {
                float xlo = h ? xv[i].z : xv[i].x;
                float xhi = h ? xv[i].w : xv[i].y;
                unsigned long long a0 = pk2(xlo, xlo);
                unsigned long long a1 = pk2(xhi, xhi);
#pragma unroll
                for (int j = 0; j < NP; j++) {
                    fma2(acc2[i][j], a0, wv0[j]);
                    fma2(acc2[i][j], a1, wv1[j]);
                }
            }
        }
    }

#pragma unroll
    for (int i = 0; i < 4; i++) {
        int node = n0 + i;
        if (node < n) {
#pragma unroll
            for (int j = 0; j < NP; j++) {
                float lo, hi;
                upk2(acc2[i][j], lo, hi);
                float* op = &out[(size_t)node * OUT + jg * TJ + 2 * j];
                float b0, b1;
                if (ADD) {
                    float2 old = *reinterpret_cast<const float2*>(op);
                    b0 = old.x; b1 = old.y;
                } else {
                    b0 = sB[jg * TJ + 2 * j]; b1 = sB[jg * TJ + 2 * j + 1];
                }
                float v0 = lo + b0;
                float v1 = hi + b1;
                if (RELU) { v0 = fmaxf(v0, 0.f); v1 = fmaxf(v1, 0.f); }
                *reinterpret_cast<float2*>(op) = make_float2(v0, v1);
            }
        }
    }
}

// ---------------- host launch ----------------
static inline int smem_bytes(int IN, int OUT) {
    return (IN * OUT + OUT) * (int)sizeof(float);
}

extern "C" void kernel_launch(void* const* d_in, const int* in_sizes, int n_in,
                              void* d_out, int out_size) {
    const float* x        = (const float*)d_in[0];
    const int*   ei       = (const int*)d_in[1];   // int32 (JAX x64 disabled)
    const float* W1_pool  = (const float*)d_in[2];
    const float* b1_pool  = (const float*)d_in[3];
    const float* W1_self  = (const float*)d_in[4];
    const float* W1_neigh = (const float*)d_in[5];
    const float* b1       = (const float*)d_in[6];
    const float* W2_pool  = (const float*)d_in[7];
    const float* b2_pool  = (const float*)d_in[8];
    const float* W2_self  = (const float*)d_in[9];
    const float* W2_neigh = (const float*)d_in[10];
    const float* b2       = (const float*)d_in[11];
    const float* W3_self  = (const float*)d_in[12];
    const float* W3_neigh = (const float*)d_in[13];
    const float* b3       = (const float*)d_in[14];

    int N = in_sizes[0] / 64;
    int E = in_sizes[1] / 2;
    if (N > MAXN) N = MAXN;
    if (E > MAXE) E = MAXE;

    const int* src = ei;        // row 0
    const int* dst = ei + E;    // row 1

    float *m, *agg, *h1, *h2, *agg3;
    int *rowptr, *deg, *scantmp, *bsum, *csrc;
    cudaGetSymbolAddress((void**)&m, g_m);
    cudaGetSymbolAddress((void**)&agg, g_agg);
    cudaGetSymbolAddress((void**)&h1, g_h1);
    cudaGetSymbolAddress((void**)&h2, g_h2);
    cudaGetSymbolAddress((void**)&agg3, g_agg3);
    cudaGetSymbolAddress((void**)&rowptr, g_rowptr);
    cudaGetSymbolAddress((void**)&deg, g_deg);
    cudaGetSymbolAddress((void**)&scantmp, g_scantmp);
    cudaGetSymbolAddress((void**)&bsum, g_bsum);
    cudaGetSymbolAddress((void**)&csrc, g_csrc);

    // one-time side stream + events (created on first, uncaptured, call;
    // host-side objects only — no device memory)
    static cudaStream_t sS = nullptr;
    static cudaEvent_t evFork, evCSR, evSelf1, evAdd1, evSelf2, evAdd2, evSelf3;
    if (!sS) {
        cudaStreamCreateWithFlags(&sS, cudaStreamNonBlocking);
        cudaEventCreateWithFlags(&evFork, cudaEventDisableTiming);
        cudaEventCreateWithFlags(&evCSR, cudaEventDisableTiming);
        cudaEventCreateWithFlags(&evSelf1, cudaEventDisableTiming);
        cudaEventCreateWithFlags(&evAdd1, cudaEventDisableTiming);
        cudaEventCreateWithFlags(&evAdd2, cudaEventDisableTiming);
        cudaEventCreateWithFlags(&evSelf2, cudaEventDisableTiming);
        cudaEventCreateWithFlags(&evSelf3, cudaEventDisableTiming);
    }

    int e4blocks = ((E + 3) / 4 + 255) / 256;
    int nblocks256 = (N + 255) / 256;
    int nblocks128 = (N + 127) / 128;
    int nbScan = (N + 511) / 512;
    int aggBlocks = (N + 7) / 8;

    // ---- fork ----
    cudaEventRecord(evFork, 0);
    cudaStreamWaitEvent(sS, evFork, 0);

    // side stream: CSR build, then layer-1 self GEMM (needs only x)
    cudaMemsetAsync(deg, 0, (size_t)N * sizeof(int), sS);
    k_hist<<<e4blocks, 256, 0, sS>>>(dst, deg, E, N);
    k_scan1<<<nbScan, 512, 0, sS>>>(deg, scantmp, bsum, N);
    k_scan2<<<1, 256, 0, sS>>>(bsum, nbScan);
    k_scan3<<<nblocks256, 256, 0, sS>>>(scantmp, deg, rowptr, bsum, N, E);
    k_scatter<<<e4blocks, 256, 0, sS>>>(src, dst, deg, csrc, E, N);
    cudaEventRecord(evCSR, sS);
    k_gemm<64, 64, false, false><<<nblocks128, 256, smem_bytes(64, 64), sS>>>(
        (const float4*)x, W1_self, b1, h1, N);   // h1 partial
    cudaEventRecord(evSelf1, sS);

    // main stream: layer-1 pool GEMM (concurrent with CSR)
    k_gemm<64, 64, true, false><<<nblocks128, 256, smem_bytes(64, 64)>>>(
        (const float4*)x, W1_pool, b1_pool, m, N);

    // agg1 needs m (main) + CSR (side)
    cudaStreamWaitEvent(0, evCSR, 0);
    k_agg_max64<<<aggBlocks, 256>>>((const float4*)m, (float4*)agg, rowptr, csrc, N);
    // add1 needs agg + h1 partial
    cudaStreamWaitEvent(0, evSelf1, 0);
    k_gemm<64, 64, true, true><<<nblocks128, 256, smem_bytes(64, 64)>>>(
        (const float4*)agg, W1_neigh, nullptr, h1, N);   // h1 = relu(h1 + agg@Wn)
    cudaEventRecord(evAdd1, 0);

    // side stream: layer-2 self GEMM (needs h1)
    cudaStreamWaitEvent(sS, evAdd1, 0);
    k_gemm<64, 32, false, false><<<nblocks128, 256, smem_bytes(64, 32), sS>>>(
        (const float4*)h1, W2_self, b2, h2, N);   // h2 partial
    cudaEventRecord(evSelf2, sS);

    // main: layer-2 pool GEMM + agg2
    k_gemm<64, 64, true, false><<<nblocks128, 256, smem_bytes(64, 64)>>>(
        (const float4*)h1, W2_pool, b2_pool, m, N);
    k_agg_max64<<<aggBlocks, 256>>>((const float4*)m, (float4*)agg, rowptr, csrc, N);
    cudaStreamWaitEvent(0, evSelf2, 0);
    k_gemm<64, 32, false, true><<<nblocks128, 256, smem_bytes(64, 32)>>>(
        (const float4*)agg, W2_neigh, nullptr, h2, N);   // h2 final
    cudaEventRecord(evAdd2, 0);

    // side stream: layer-3 self GEMM (needs h2)
    cudaStreamWaitEvent(sS, evAdd2, 0);
    k_gemm<32, 32, false, false><<<nblocks128, 256, smem_bytes(32, 32), sS>>>(
        (const float4*)h2, W3_self, b3, (float*)d_out, N);  // out partial
    cudaEventRecord(evSelf3, sS);

    // main: agg3 (mean) + final add
    k_agg_mean32<<<aggBlocks, 256>>>((const float4*)h2, (float4*)agg3, rowptr, csrc, N);
    cudaStreamWaitEvent(0, evSelf3, 0);
    k_gemm<32, 32, false, true><<<nblocks128, 256, smem_bytes(32, 32)>>>(
        (const float4*)agg3, W3_neigh, nullptr, (float*)d_out, N);  // out final
}